// round 11
// baseline (speedup 1.0000x reference)
#include <cuda_runtime.h>
#include <cuda_bf16.h>
#include <cstdint>

// Problem shape (fixed)
#define B_TOT 64
#define T_TOT 2048
#define D_DIM 256
#define U_DIM 256
#define M_TOT (B_TOT * T_TOT)   // 131072

// Scratch: projections [3][M][U] fp32 = 402 MB, weights transposed+split bf16,
// plus carried scan state h for slab pipelining.
__device__ float g_proj[3ull * M_TOT * U_DIM];
__device__ __nv_bfloat16 g_wt_hi[3 * U_DIM * D_DIM];   // [n=768][k=256]
__device__ __nv_bfloat16 g_wt_lo[3 * U_DIM * D_DIM];
__device__ float g_h[B_TOT * U_DIM];

// ---------------------------------------------------------------------------
// PTX helpers — base sm_103-safe only (cp.async, ldmatrix, mma.sync, mufu).
// ---------------------------------------------------------------------------
__device__ __forceinline__ uint32_t smem_u32(const void* p) {
    uint32_t a;
    asm("{ .reg .u64 t; cvta.to.shared.u64 t, %1; cvt.u32.u64 %0, t; }" : "=r"(a) : "l"(p));
    return a;
}

#define CP_ASYNC16(dst, src) \
    asm volatile("cp.async.cg.shared.global [%0], [%1], 16;" :: "r"(dst), "l"(src) : "memory")
#define CP_ASYNC_COMMIT()   asm volatile("cp.async.commit_group;" ::: "memory")
#define CP_ASYNC_WAIT_ALL() asm volatile("cp.async.wait_all;" ::: "memory")

#define LDMATRIX_X4(r0, r1, r2, r3, addr) \
    asm volatile("ldmatrix.sync.aligned.m8n8.x4.shared.b16 {%0,%1,%2,%3}, [%4];" \
                 : "=r"(r0), "=r"(r1), "=r"(r2), "=r"(r3) : "r"(addr))

__device__ __forceinline__ void mma_bf16(float* d, const uint32_t* a, const uint32_t* b) {
    asm volatile(
        "mma.sync.aligned.m16n8k16.row.col.f32.bf16.bf16.f32 "
        "{%0,%1,%2,%3}, {%4,%5,%6,%7}, {%8,%9}, {%0,%1,%2,%3};"
        : "+f"(d[0]), "+f"(d[1]), "+f"(d[2]), "+f"(d[3])
        : "r"(a[0]), "r"(a[1]), "r"(a[2]), "r"(a[3]), "r"(b[0]), "r"(b[1]));
}

__device__ __forceinline__ float ex2a(float x) {
    float y; asm("ex2.approx.f32 %0, %1;" : "=f"(y) : "f"(x)); return y;
}
__device__ __forceinline__ float rcpa(float x) {
    float y; asm("rcp.approx.f32 %0, %1;" : "=f"(y) : "f"(x)); return y;
}

__device__ __forceinline__ unsigned short bf16_bits(float f) {
    __nv_bfloat16 b = __float2bfloat16(f);
    return *reinterpret_cast<unsigned short*>(&b);
}

// ---------------------------------------------------------------------------
// Kernel 0: weight prep. Wt[n][k] = W[k][u] transposed, split into bf16 hi/lo.
// ---------------------------------------------------------------------------
__global__ __launch_bounds__(256) void bru_wprep(
    const float* __restrict__ kz, const float* __restrict__ kr, const float* __restrict__ kh)
{
    int i = blockIdx.x * 256 + threadIdx.x;       // [0, 768*256)
    int w = i >> 16;
    int k = (i >> 8) & 255;
    int u = i & 255;
    const float* W = (w == 0) ? kz : (w == 1) ? kr : kh;
    float v = W[k * 256 + u];
    __nv_bfloat16 hi = __float2bfloat16(v);
    float lo = v - __bfloat162float(hi);
    int n = w * 256 + u;
    g_wt_hi[n * 256 + k] = hi;
    g_wt_lo[n * 256 + k] = __float2bfloat16(lo);
}

// ---------------------------------------------------------------------------
// Kernel A: mma.sync bf16-split GEMM, time-slab version.
//   grid (6, 64, ntb): nt = x, batch = y, tblock-in-slab = z.
//   m-tile = batch*16 + tb0 + z  (each tile covers 128 timesteps of one batch).
// ---------------------------------------------------------------------------
#define BM 128
#define BN 128
#define BK 32
#define RS 40                        // row stride in bf16 elems (80 B)
#define TILE_B (128 * RS * 2)        // 10240 B per array
#define STAGE_B (4 * TILE_B)         // Ahi, Alo, Bhi, Blo = 40960 B
#define SMEM_SZ (2 * STAGE_B)        // 81920 B

__global__ __launch_bounds__(256) void bru_gemm_mma(const float* __restrict__ X, int tb0)
{
    extern __shared__ char sm[];
    const uint32_t smb = smem_u32(sm);
    const int tid  = threadIdx.x;
    const int wid  = tid >> 5;
    const int lane = tid & 31;

    const int nt = blockIdx.x;            // 0..5 over N=768
    const int mt = blockIdx.y * 16 + tb0 + blockIdx.z;
    const int m0 = mt * BM;
    const int n0 = nt * BN;

    const int wm = (wid >> 1) * 32;
    const int wn = (wid & 1) * 64;

    auto OA_HI = [&](int s) { return smb + s * STAGE_B; };
    auto OA_LO = [&](int s) { return smb + s * STAGE_B + TILE_B; };
    auto OB_HI = [&](int s) { return smb + s * STAGE_B + 2 * TILE_B; };
    auto OB_LO = [&](int s) { return smb + s * STAGE_B + 3 * TILE_B; };

    float4 areg[4];
    auto ldgA = [&](int c) {
        const int kc = c * BK;
#pragma unroll
        for (int i = 0; i < 4; i++) {
            int s = i * 256 + tid;
            int row = s >> 3, c4 = s & 7;
            areg[i] = *(const float4*)(X + (size_t)(m0 + row) * D_DIM + kc + c4 * 4);
        }
    };
    auto stsA = [&](int st) {
#pragma unroll
        for (int i = 0; i < 4; i++) {
            int s = i * 256 + tid;
            int row = s >> 3, c4 = s & 7;
            uint32_t off = (uint32_t)(row * (RS * 2) + c4 * 8);
            float f[4] = {areg[i].x, areg[i].y, areg[i].z, areg[i].w};
            unsigned short h[4], l[4];
#pragma unroll
            for (int j = 0; j < 4; j++) {
                h[j] = bf16_bits(f[j]);
                __nv_bfloat16 hb = *reinterpret_cast<__nv_bfloat16*>(&h[j]);
                l[j] = bf16_bits(f[j] - __bfloat162float(hb));
            }
            uint32_t ph0 = (uint32_t)h[0] | ((uint32_t)h[1] << 16);
            uint32_t ph1 = (uint32_t)h[2] | ((uint32_t)h[3] << 16);
            uint32_t pl0 = (uint32_t)l[0] | ((uint32_t)l[1] << 16);
            uint32_t pl1 = (uint32_t)l[2] | ((uint32_t)l[3] << 16);
            asm volatile("st.shared.v2.b32 [%0], {%1, %2};" :: "r"(OA_HI(st) + off), "r"(ph0), "r"(ph1) : "memory");
            asm volatile("st.shared.v2.b32 [%0], {%1, %2};" :: "r"(OA_LO(st) + off), "r"(pl0), "r"(pl1) : "memory");
        }
    };
    auto cpB = [&](int c, int st) {
        const int kc = c * BK;
#pragma unroll
        for (int i = 0; i < 2; i++) {
            int g = i * 256 + tid;
            int row = g >> 2, seg = g & 3;
            size_t e = (size_t)(n0 + row) * D_DIM + kc + seg * 8;
            uint32_t off = (uint32_t)(row * (RS * 2) + seg * 16);
            CP_ASYNC16(OB_HI(st) + off, (const char*)g_wt_hi + e * 2);
            CP_ASYNC16(OB_LO(st) + off, (const char*)g_wt_lo + e * 2);
        }
        CP_ASYNC_COMMIT();
    };

    ldgA(0);
    cpB(0, 0);
    stsA(0);
    CP_ASYNC_WAIT_ALL();
    __syncthreads();

    float acc[2][8][4];
#pragma unroll
    for (int mi = 0; mi < 2; mi++)
#pragma unroll
        for (int ni = 0; ni < 8; ni++)
#pragma unroll
            for (int r = 0; r < 4; r++) acc[mi][ni][r] = 0.0f;

    const int lrow = lane & 15;
    const int lhal = (lane >> 4) << 4;

    for (int c = 0; c < 8; c++) {
        const int st = c & 1;
        if (c < 7) { cpB(c + 1, st ^ 1); ldgA(c + 1); }

#pragma unroll
        for (int kk = 0; kk < 2; kk++) {
            const uint32_t kb = (uint32_t)(kk * 32);
            uint32_t ah[2][4], al[2][4], bh[4][4], bl[4][4];
#pragma unroll
            for (int mi = 0; mi < 2; mi++) {
                uint32_t ra = (uint32_t)((wm + mi * 16 + lrow) * (RS * 2)) + kb + lhal;
                LDMATRIX_X4(ah[mi][0], ah[mi][1], ah[mi][2], ah[mi][3], OA_HI(st) + ra);
                LDMATRIX_X4(al[mi][0], al[mi][1], al[mi][2], al[mi][3], OA_LO(st) + ra);
            }
#pragma unroll
            for (int nj = 0; nj < 4; nj++) {
                uint32_t rb = (uint32_t)((wn + nj * 16 + lrow) * (RS * 2)) + kb + lhal;
                LDMATRIX_X4(bh[nj][0], bh[nj][1], bh[nj][2], bh[nj][3], OB_HI(st) + rb);
                LDMATRIX_X4(bl[nj][0], bl[nj][1], bl[nj][2], bl[nj][3], OB_LO(st) + rb);
            }
#pragma unroll
            for (int mi = 0; mi < 2; mi++)
#pragma unroll
                for (int nj = 0; nj < 4; nj++) {
                    uint32_t b0h[2] = {bh[nj][0], bh[nj][2]};
                    uint32_t b1h[2] = {bh[nj][1], bh[nj][3]};
                    uint32_t b0l[2] = {bl[nj][0], bl[nj][2]};
                    uint32_t b1l[2] = {bl[nj][1], bl[nj][3]};
                    mma_bf16(acc[mi][nj * 2 + 0], ah[mi], b0h);
                    mma_bf16(acc[mi][nj * 2 + 0], ah[mi], b0l);
                    mma_bf16(acc[mi][nj * 2 + 0], al[mi], b0h);
                    mma_bf16(acc[mi][nj * 2 + 1], ah[mi], b1h);
                    mma_bf16(acc[mi][nj * 2 + 1], ah[mi], b1l);
                    mma_bf16(acc[mi][nj * 2 + 1], al[mi], b1h);
                }
        }

        if (c < 7) {
            stsA(st ^ 1);
            CP_ASYNC_WAIT_ALL();
            __syncthreads();
        }
    }

    const int w = nt >> 1;
    const int u0 = (nt & 1) * BN;
    float* Out = g_proj + (size_t)w * M_TOT * U_DIM;

    const int trow = lane >> 2;
    const int tcol = (lane & 3) * 2;
#pragma unroll
    for (int mi = 0; mi < 2; mi++)
#pragma unroll
        for (int ni = 0; ni < 8; ni++) {
            int r = m0 + wm + mi * 16 + trow;
            int cc = u0 + wn + ni * 8 + tcol;
            float2 v0 = make_float2(acc[mi][ni][0], acc[mi][ni][1]);
            float2 v1 = make_float2(acc[mi][ni][2], acc[mi][ni][3]);
            *(float2*)(Out + (size_t)r * U_DIM + cc) = v0;
            *(float2*)(Out + (size_t)(r + 8) * U_DIM + cc) = v1;
        }
}

// ---------------------------------------------------------------------------
// Kernel B: scan time-slab [t_start, t_start + t_len).  h carried in g_h.
//   PF=16 register prefetch; exp2-domain math (unchanged numerics).
// ---------------------------------------------------------------------------
#define PF 16

__global__ __launch_bounds__(256) void bru_scan_slab(
    const float* __restrict__ mz, const float* __restrict__ mr,
    const float* __restrict__ bz, const float* __restrict__ br,
    const float* __restrict__ bh,
    float* __restrict__ out, int t_start, int t_len)
{
    const int b = blockIdx.x;        // batch
    const int u = threadIdx.x;       // unit

    const size_t base = (size_t)b * T_TOT * U_DIM + (size_t)t_start * U_DIM + u;
    const float* __restrict__ pz = g_proj + base;
    const float* __restrict__ pr = g_proj + (size_t)1 * M_TOT * U_DIM + base;
    const float* __restrict__ ph = g_proj + (size_t)2 * M_TOT * U_DIM + base;
    float* __restrict__ po = out + base;

    const float C2 = 2.8853900817779268f;    // 2*log2(e)
    const float CN = -1.4426950408889634f;   // -log2(e)

    const float mr2 = mr[u] * C2, br2 = br[u] * C2;   // r-path, exp2 domain
    const float mzn = mz[u] * CN, bzn = bz[u] * CN;   // z-path, exp2 domain
    const float bh2 = bh[u] * C2;                     // h-path, exp2 domain

    float qz[PF], qr[PF], qh[PF];
#pragma unroll
    for (int j = 0; j < PF; j++) {
        qz[j] = pz[(size_t)j * U_DIM];
        qr[j] = pr[(size_t)j * U_DIM];
        qh[j] = ph[(size_t)j * U_DIM];
    }

    float h = (t_start == 0) ? 0.0f : g_h[b * U_DIM + u];

#pragma unroll 1
    for (int t0 = 0; t0 < t_len - PF; t0 += PF) {
#pragma unroll
        for (int j = 0; j < PF; j++) {
            const float vz = qz[j], vr = qr[j], vh = qh[j];
            qz[j] = pz[(size_t)(j + PF) * U_DIM];
            qr[j] = pr[(size_t)(j + PF) * U_DIM];
            qh[j] = ph[(size_t)(j + PF) * U_DIM];

            const float hs   = h * C2;
            const float hbase= fmaf(vh, C2, bh2);
            const float pre2 = fmaf(2.0f, hs, hbase);
            const float hm1  = h - 1.0f;

            const float ar2 = fmaf(h, mr2, fmaf(vr, C2, br2));
            const float tr  = rcpa(ex2a(ar2) + 1.0f);

            const float azn = fmaf(h, mzn, fmaf(vz, CN, bzn));
            const float z   = rcpa(ex2a(azn) + 1.0f);

            const float ah2 = fmaf(-2.0f * tr, hs, pre2);
            const float th  = rcpa(ex2a(ah2) + 1.0f);
            const float hh  = fmaf(-2.0f, th, 1.0f);
            const float d   = fmaf(2.0f, th, hm1);

            h = fmaf(z, d, hh);
            po[(size_t)j * U_DIM] = h;
        }
        pz += PF * U_DIM; pr += PF * U_DIM; ph += PF * U_DIM; po += PF * U_DIM;
    }

    // tail: last PF steps, no prefetch
#pragma unroll
    for (int j = 0; j < PF; j++) {
        const float hs   = h * C2;
        const float hbase= fmaf(qh[j], C2, bh2);
        const float pre2 = fmaf(2.0f, hs, hbase);
        const float hm1  = h - 1.0f;

        const float ar2 = fmaf(h, mr2, fmaf(qr[j], C2, br2));
        const float tr  = rcpa(ex2a(ar2) + 1.0f);

        const float azn = fmaf(h, mzn, fmaf(qz[j], CN, bzn));
        const float z   = rcpa(ex2a(azn) + 1.0f);

        const float ah2 = fmaf(-2.0f * tr, hs, pre2);
        const float th  = rcpa(ex2a(ah2) + 1.0f);
        const float hh  = fmaf(-2.0f, th, 1.0f);
        const float d   = fmaf(2.0f, th, hm1);

        h = fmaf(z, d, hh);
        po[(size_t)j * U_DIM] = h;
    }

    g_h[b * U_DIM + u] = h;
}

// ---------------------------------------------------------------------------
// Host: fork-join pipelined launch. GEMM slabs on the main stream, scan slabs
// on a side stream gated by per-slab events (graph edges under capture).
// Slab sizes (timesteps): 512,512,512,256,128,128 — descending so the exposed
// final scan slab is small.
// ---------------------------------------------------------------------------
#define NSLAB 6
static const int slab_tb0[NSLAB] = {0, 4, 8, 12, 14, 15};
static const int slab_ntb[NSLAB] = {4, 4, 4, 2, 1, 1};

struct PipeCtx {
    cudaStream_t s2;
    cudaEvent_t  evG[NSLAB];
    cudaEvent_t  evS;
};
static PipeCtx* make_ctx() {
    static PipeCtx c;
    cudaStreamCreateWithFlags(&c.s2, cudaStreamNonBlocking);
    for (int i = 0; i < NSLAB; i++) cudaEventCreateWithFlags(&c.evG[i], cudaEventDisableTiming);
    cudaEventCreateWithFlags(&c.evS, cudaEventDisableTiming);
    cudaFuncSetAttribute(bru_gemm_mma, cudaFuncAttributeMaxDynamicSharedMemorySize, SMEM_SZ);
    return &c;
}

extern "C" void kernel_launch(void* const* d_in, const int* in_sizes, int n_in,
                              void* d_out, int out_size)
{
    const float* x  = (const float*)d_in[0];
    const float* kz = (const float*)d_in[1];
    const float* kr = (const float*)d_in[2];
    const float* kh = (const float*)d_in[3];
    const float* mz = (const float*)d_in[4];
    const float* mr = (const float*)d_in[5];
    const float* bz = (const float*)d_in[6];
    const float* br = (const float*)d_in[7];
    const float* bh = (const float*)d_in[8];
    float* out = (float*)d_out;

    static PipeCtx* ctx = make_ctx();   // created on first (uncaptured) call

    bru_wprep<<<768, 256>>>(kz, kr, kh);

    for (int k = 0; k < NSLAB; k++) {
        dim3 gg(6, 64, slab_ntb[k]);
        bru_gemm_mma<<<gg, 256, SMEM_SZ>>>(x, slab_tb0[k]);
        cudaEventRecord(ctx->evG[k], 0);
        cudaStreamWaitEvent(ctx->s2, ctx->evG[k], 0);
        bru_scan_slab<<<B_TOT, 256, 0, ctx->s2>>>(mz, mr, bz, br, bh, out,
                                                  slab_tb0[k] * 128,
                                                  slab_ntb[k] * 128);
    }
    cudaEventRecord(ctx->evS, ctx->s2);
    cudaStreamWaitEvent(0, ctx->evS, 0);
}

// round 13
// speedup vs baseline: 1.0723x; 1.0723x over previous
#include <cuda_runtime.h>
#include <cuda_bf16.h>
#include <cstdint>

// Problem shape (fixed)
#define B_TOT 64
#define T_TOT 2048
#define D_DIM 256
#define U_DIM 256
#define M_TOT (B_TOT * T_TOT)   // 131072

// Scratch: projections [3][M][U] fp32 = 402 MB, weights transposed+split bf16.
__device__ float g_proj[3ull * M_TOT * U_DIM];
__device__ __nv_bfloat16 g_wt_hi[3 * U_DIM * D_DIM];   // [n=768][k=256]
__device__ __nv_bfloat16 g_wt_lo[3 * U_DIM * D_DIM];

// ---------------------------------------------------------------------------
// PTX helpers — base sm_103-safe only (cp.async, ldmatrix, mma.sync, mufu).
// ---------------------------------------------------------------------------
__device__ __forceinline__ uint32_t smem_u32(const void* p) {
    uint32_t a;
    asm("{ .reg .u64 t; cvta.to.shared.u64 t, %1; cvt.u32.u64 %0, t; }" : "=r"(a) : "l"(p));
    return a;
}

#define CP_ASYNC16(dst, src) \
    asm volatile("cp.async.cg.shared.global [%0], [%1], 16;" :: "r"(dst), "l"(src) : "memory")
#define CP_ASYNC_COMMIT()   asm volatile("cp.async.commit_group;" ::: "memory")
#define CP_ASYNC_WAIT_ALL() asm volatile("cp.async.wait_all;" ::: "memory")

#define LDMATRIX_X4(r0, r1, r2, r3, addr) \
    asm volatile("ldmatrix.sync.aligned.m8n8.x4.shared.b16 {%0,%1,%2,%3}, [%4];" \
                 : "=r"(r0), "=r"(r1), "=r"(r2), "=r"(r3) : "r"(addr))

__device__ __forceinline__ void mma_bf16(float* d, const uint32_t* a, const uint32_t* b) {
    asm volatile(
        "mma.sync.aligned.m16n8k16.row.col.f32.bf16.bf16.f32 "
        "{%0,%1,%2,%3}, {%4,%5,%6,%7}, {%8,%9}, {%0,%1,%2,%3};"
        : "+f"(d[0]), "+f"(d[1]), "+f"(d[2]), "+f"(d[3])
        : "r"(a[0]), "r"(a[1]), "r"(a[2]), "r"(a[3]), "r"(b[0]), "r"(b[1]));
}

__device__ __forceinline__ float ex2a(float x) {
    float y; asm("ex2.approx.f32 %0, %1;" : "=f"(y) : "f"(x)); return y;
}
__device__ __forceinline__ float rcpa(float x) {
    float y; asm("rcp.approx.f32 %0, %1;" : "=f"(y) : "f"(x)); return y;
}

__device__ __forceinline__ unsigned short bf16_bits(float f) {
    __nv_bfloat16 b = __float2bfloat16(f);
    return *reinterpret_cast<unsigned short*>(&b);
}

// ---------------------------------------------------------------------------
// Kernel 0: weight prep. Wt[n][k] = W[k][u] transposed, split into bf16 hi/lo.
// ---------------------------------------------------------------------------
__global__ __launch_bounds__(256) void bru_wprep(
    const float* __restrict__ kz, const float* __restrict__ kr, const float* __restrict__ kh)
{
    int i = blockIdx.x * 256 + threadIdx.x;       // [0, 768*256)
    int w = i >> 16;
    int k = (i >> 8) & 255;
    int u = i & 255;
    const float* W = (w == 0) ? kz : (w == 1) ? kr : kh;
    float v = W[k * 256 + u];
    __nv_bfloat16 hi = __float2bfloat16(v);
    float lo = v - __bfloat162float(hi);
    int n = w * 256 + u;
    g_wt_hi[n * 256 + k] = hi;
    g_wt_lo[n * 256 + k] = __float2bfloat16(lo);
}

// ---------------------------------------------------------------------------
// Kernel A: mma.sync bf16-split GEMM.  C[M,768] = X[M,256] @ Wt^T
//   BM=128, BN=128, BK=32, 256 thr, 8 warps (4m x 2n), warp tile m32 x n64.
//   3 passes: Ahi*Bhi + Ahi*Blo + Alo*Bhi, fp32 accum.
//   __launch_bounds__(256, 2): cap regs at 128 -> 2 CTAs/SM so a co-resident
//   CTA's HMMAs fill this CTA's sync/ldmatrix/epilogue bubbles.
// ---------------------------------------------------------------------------
#define BM 128
#define BN 128
#define BK 32
#define RS 40                        // row stride in bf16 elems (80 B)
#define TILE_B (128 * RS * 2)        // 10240 B per array
#define STAGE_B (4 * TILE_B)         // Ahi, Alo, Bhi, Blo = 40960 B
#define SMEM_SZ (2 * STAGE_B)        // 81920 B

__global__ __launch_bounds__(256, 2) void bru_gemm_mma(const float* __restrict__ X)
{
    extern __shared__ char sm[];
    const uint32_t smb = smem_u32(sm);
    const int tid  = threadIdx.x;
    const int wid  = tid >> 5;
    const int lane = tid & 31;

    const int nt = blockIdx.x;            // 0..5 over N=768
    const int m0 = blockIdx.y * BM;
    const int n0 = nt * BN;

    const int wm = (wid >> 1) * 32;
    const int wn = (wid & 1) * 64;

    auto OA_HI = [&](int s) { return smb + s * STAGE_B; };
    auto OA_LO = [&](int s) { return smb + s * STAGE_B + TILE_B; };
    auto OB_HI = [&](int s) { return smb + s * STAGE_B + 2 * TILE_B; };
    auto OB_LO = [&](int s) { return smb + s * STAGE_B + 3 * TILE_B; };

    float4 areg[4];
    auto ldgA = [&](int c) {
        const int kc = c * BK;
#pragma unroll
        for (int i = 0; i < 4; i++) {
            int s = i * 256 + tid;
            int row = s >> 3, c4 = s & 7;
            areg[i] = *(const float4*)(X + (size_t)(m0 + row) * D_DIM + kc + c4 * 4);
        }
    };
    auto stsA = [&](int st) {
#pragma unroll
        for (int i = 0; i < 4; i++) {
            int s = i * 256 + tid;
            int row = s >> 3, c4 = s & 7;
            uint32_t off = (uint32_t)(row * (RS * 2) + c4 * 8);
            float f[4] = {areg[i].x, areg[i].y, areg[i].z, areg[i].w};
            unsigned short h[4], l[4];
#pragma unroll
            for (int j = 0; j < 4; j++) {
                h[j] = bf16_bits(f[j]);
                __nv_bfloat16 hb = *reinterpret_cast<__nv_bfloat16*>(&h[j]);
                l[j] = bf16_bits(f[j] - __bfloat162float(hb));
            }
            uint32_t ph0 = (uint32_t)h[0] | ((uint32_t)h[1] << 16);
            uint32_t ph1 = (uint32_t)h[2] | ((uint32_t)h[3] << 16);
            uint32_t pl0 = (uint32_t)l[0] | ((uint32_t)l[1] << 16);
            uint32_t pl1 = (uint32_t)l[2] | ((uint32_t)l[3] << 16);
            asm volatile("st.shared.v2.b32 [%0], {%1, %2};" :: "r"(OA_HI(st) + off), "r"(ph0), "r"(ph1) : "memory");
            asm volatile("st.shared.v2.b32 [%0], {%1, %2};" :: "r"(OA_LO(st) + off), "r"(pl0), "r"(pl1) : "memory");
        }
    };
    auto cpB = [&](int c, int st) {
        const int kc = c * BK;
#pragma unroll
        for (int i = 0; i < 2; i++) {
            int g = i * 256 + tid;
            int row = g >> 2, seg = g & 3;
            size_t e = (size_t)(n0 + row) * D_DIM + kc + seg * 8;
            uint32_t off = (uint32_t)(row * (RS * 2) + seg * 16);
            CP_ASYNC16(OB_HI(st) + off, (const char*)g_wt_hi + e * 2);
            CP_ASYNC16(OB_LO(st) + off, (const char*)g_wt_lo + e * 2);
        }
        CP_ASYNC_COMMIT();
    };

    ldgA(0);
    cpB(0, 0);
    stsA(0);
    CP_ASYNC_WAIT_ALL();
    __syncthreads();

    float acc[2][8][4];
#pragma unroll
    for (int mi = 0; mi < 2; mi++)
#pragma unroll
        for (int ni = 0; ni < 8; ni++)
#pragma unroll
            for (int r = 0; r < 4; r++) acc[mi][ni][r] = 0.0f;

    const int lrow = lane & 15;
    const int lhal = (lane >> 4) << 4;

    for (int c = 0; c < 8; c++) {
        const int st = c & 1;
        if (c < 7) { cpB(c + 1, st ^ 1); ldgA(c + 1); }

#pragma unroll
        for (int kk = 0; kk < 2; kk++) {
            const uint32_t kb = (uint32_t)(kk * 32);
            uint32_t ah[2][4], al[2][4], bh[4][4], bl[4][4];
#pragma unroll
            for (int mi = 0; mi < 2; mi++) {
                uint32_t ra = (uint32_t)((wm + mi * 16 + lrow) * (RS * 2)) + kb + lhal;
                LDMATRIX_X4(ah[mi][0], ah[mi][1], ah[mi][2], ah[mi][3], OA_HI(st) + ra);
                LDMATRIX_X4(al[mi][0], al[mi][1], al[mi][2], al[mi][3], OA_LO(st) + ra);
            }
#pragma unroll
            for (int nj = 0; nj < 4; nj++) {
                uint32_t rb = (uint32_t)((wn + nj * 16 + lrow) * (RS * 2)) + kb + lhal;
                LDMATRIX_X4(bh[nj][0], bh[nj][1], bh[nj][2], bh[nj][3], OB_HI(st) + rb);
                LDMATRIX_X4(bl[nj][0], bl[nj][1], bl[nj][2], bl[nj][3], OB_LO(st) + rb);
            }
#pragma unroll
            for (int mi = 0; mi < 2; mi++)
#pragma unroll
                for (int nj = 0; nj < 4; nj++) {
                    uint32_t b0h[2] = {bh[nj][0], bh[nj][2]};
                    uint32_t b1h[2] = {bh[nj][1], bh[nj][3]};
                    uint32_t b0l[2] = {bl[nj][0], bl[nj][2]};
                    uint32_t b1l[2] = {bl[nj][1], bl[nj][3]};
                    mma_bf16(acc[mi][nj * 2 + 0], ah[mi], b0h);
                    mma_bf16(acc[mi][nj * 2 + 0], ah[mi], b0l);
                    mma_bf16(acc[mi][nj * 2 + 0], al[mi], b0h);
                    mma_bf16(acc[mi][nj * 2 + 1], ah[mi], b1h);
                    mma_bf16(acc[mi][nj * 2 + 1], ah[mi], b1l);
                    mma_bf16(acc[mi][nj * 2 + 1], al[mi], b1h);
                }
        }

        if (c < 7) {
            stsA(st ^ 1);
            CP_ASYNC_WAIT_ALL();
            __syncthreads();
        }
    }

    const int w = nt >> 1;
    const int u0 = (nt & 1) * BN;
    float* Out = g_proj + (size_t)w * M_TOT * U_DIM;

    const int trow = lane >> 2;
    const int tcol = (lane & 3) * 2;
#pragma unroll
    for (int mi = 0; mi < 2; mi++)
#pragma unroll
        for (int ni = 0; ni < 8; ni++) {
            int r = m0 + wm + mi * 16 + trow;
            int cc = u0 + wn + ni * 8 + tcol;
            float2 v0 = make_float2(acc[mi][ni][0], acc[mi][ni][1]);
            float2 v1 = make_float2(acc[mi][ni][2], acc[mi][ni][3]);
            *(float2*)(Out + (size_t)r * U_DIM + cc) = v0;
            *(float2*)(Out + (size_t)(r + 8) * U_DIM + cc) = v1;
        }
}

// ---------------------------------------------------------------------------
// Kernel B: sequential scan.  PF=16 register prefetch; exp2-domain math.
// (known-good ~277 us)
// ---------------------------------------------------------------------------
#define PF 16

__global__ __launch_bounds__(256) void bru_scan(
    const float* __restrict__ mz, const float* __restrict__ mr,
    const float* __restrict__ bz, const float* __restrict__ br,
    const float* __restrict__ bh,
    float* __restrict__ out)
{
    const int b = blockIdx.x;        // batch
    const int u = threadIdx.x;       // unit

    const size_t base = (size_t)b * T_TOT * U_DIM + u;
    const float* __restrict__ pz = g_proj + base;
    const float* __restrict__ pr = g_proj + (size_t)1 * M_TOT * U_DIM + base;
    const float* __restrict__ ph = g_proj + (size_t)2 * M_TOT * U_DIM + base;
    float* __restrict__ po = out + base;

    const float C2 = 2.8853900817779268f;    // 2*log2(e)
    const float CN = -1.4426950408889634f;   // -log2(e)

    const float mr2 = mr[u] * C2, br2 = br[u] * C2;
    const float mzn = mz[u] * CN, bzn = bz[u] * CN;
    const float bh2 = bh[u] * C2;

    float qz[PF], qr[PF], qh[PF];
#pragma unroll
    for (int j = 0; j < PF; j++) {
        qz[j] = pz[(size_t)j * U_DIM];
        qr[j] = pr[(size_t)j * U_DIM];
        qh[j] = ph[(size_t)j * U_DIM];
    }

    float h = 0.0f;

#pragma unroll 1
    for (int t0 = 0; t0 < T_TOT - PF; t0 += PF) {
#pragma unroll
        for (int j = 0; j < PF; j++) {
            const float vz = qz[j], vr = qr[j], vh = qh[j];
            qz[j] = pz[(size_t)(j + PF) * U_DIM];
            qr[j] = pr[(size_t)(j + PF) * U_DIM];
            qh[j] = ph[(size_t)(j + PF) * U_DIM];

            const float hs   = h * C2;
            const float hbase= fmaf(vh, C2, bh2);
            const float pre2 = fmaf(2.0f, hs, hbase);
            const float hm1  = h - 1.0f;

            const float ar2 = fmaf(h, mr2, fmaf(vr, C2, br2));
            const float tr  = rcpa(ex2a(ar2) + 1.0f);

            const float azn = fmaf(h, mzn, fmaf(vz, CN, bzn));
            const float z   = rcpa(ex2a(azn) + 1.0f);

            const float ah2 = fmaf(-2.0f * tr, hs, pre2);
            const float th  = rcpa(ex2a(ah2) + 1.0f);
            const float hh  = fmaf(-2.0f, th, 1.0f);
            const float d   = fmaf(2.0f, th, hm1);

            h = fmaf(z, d, hh);
            po[(size_t)j * U_DIM] = h;
        }
        pz += PF * U_DIM; pr += PF * U_DIM; ph += PF * U_DIM; po += PF * U_DIM;
    }

    // tail: last PF steps, no prefetch
#pragma unroll
    for (int j = 0; j < PF; j++) {
        const float hs   = h * C2;
        const float hbase= fmaf(qh[j], C2, bh2);
        const float pre2 = fmaf(2.0f, hs, hbase);
        const float hm1  = h - 1.0f;

        const float ar2 = fmaf(h, mr2, fmaf(qr[j], C2, br2));
        const float tr  = rcpa(ex2a(ar2) + 1.0f);

        const float azn = fmaf(h, mzn, fmaf(qz[j], CN, bzn));
        const float z   = rcpa(ex2a(azn) + 1.0f);

        const float ah2 = fmaf(-2.0f * tr, hs, pre2);
        const float th  = rcpa(ex2a(ah2) + 1.0f);
        const float hh  = fmaf(-2.0f, th, 1.0f);
        const float d   = fmaf(2.0f, th, hm1);

        h = fmaf(z, d, hh);
        po[(size_t)j * U_DIM] = h;
    }
}

// ---------------------------------------------------------------------------
extern "C" void kernel_launch(void* const* d_in, const int* in_sizes, int n_in,
                              void* d_out, int out_size)
{
    const float* x  = (const float*)d_in[0];
    const float* kz = (const float*)d_in[1];
    const float* kr = (const float*)d_in[2];
    const float* kh = (const float*)d_in[3];
    const float* mz = (const float*)d_in[4];
    const float* mr = (const float*)d_in[5];
    const float* bz = (const float*)d_in[6];
    const float* br = (const float*)d_in[7];
    const float* bh = (const float*)d_in[8];
    float* out = (float*)d_out;

    // One-time setup on the first (uncaptured correctness) call; keeps the
    // captured stream free of runtime-API nodes.
    static bool init_done = (cudaFuncSetAttribute(bru_gemm_mma,
        cudaFuncAttributeMaxDynamicSharedMemorySize, SMEM_SZ) == cudaSuccess);
    (void)init_done;

    bru_wprep<<<768, 256>>>(kz, kr, kh);
    dim3 gg(6, M_TOT / BM);
    bru_gemm_mma<<<gg, 256, SMEM_SZ>>>(x);
    bru_scan<<<B_TOT, 256>>>(mz, mr, bz, br, bh, out);
}

// round 17
// speedup vs baseline: 1.2789x; 1.1927x over previous
#include <cuda_runtime.h>
#include <cuda_bf16.h>
#include <cuda_fp16.h>
#include <cstdint>

// Problem shape (fixed)
#define B_TOT 64
#define T_TOT 2048
#define D_DIM 256
#define U_DIM 256
#define M_TOT (B_TOT * T_TOT)   // 131072

// Scratch: projections [3][M][U] fp32 = 402 MB; weights transposed, fp16.
__device__ float g_proj[3ull * M_TOT * U_DIM];
__device__ __half g_wt[3 * U_DIM * D_DIM];   // [n=768][k=256], fp16 hi only

// ---------------------------------------------------------------------------
// PTX helpers — base sm_103-safe only (cp.async, ldmatrix, mma.sync, mufu).
// ---------------------------------------------------------------------------
__device__ __forceinline__ uint32_t smem_u32(const void* p) {
    uint32_t a;
    asm("{ .reg .u64 t; cvta.to.shared.u64 t, %1; cvt.u32.u64 %0, t; }" : "=r"(a) : "l"(p));
    return a;
}

#define CP_ASYNC16(dst, src) \
    asm volatile("cp.async.cg.shared.global [%0], [%1], 16;" :: "r"(dst), "l"(src) : "memory")
#define CP_ASYNC_COMMIT()   asm volatile("cp.async.commit_group;" ::: "memory")
#define CP_ASYNC_WAIT_ALL() asm volatile("cp.async.wait_all;" ::: "memory")

#define LDMATRIX_X4(r0, r1, r2, r3, addr) \
    asm volatile("ldmatrix.sync.aligned.m8n8.x4.shared.b16 {%0,%1,%2,%3}, [%4];" \
                 : "=r"(r0), "=r"(r1), "=r"(r2), "=r"(r3) : "r"(addr))

// fp16 inputs, fp32 accumulate
__device__ __forceinline__ void mma_f16(float* d, const uint32_t* a, const uint32_t* b) {
    asm volatile(
        "mma.sync.aligned.m16n8k16.row.col.f32.f16.f16.f32 "
        "{%0,%1,%2,%3}, {%4,%5,%6,%7}, {%8,%9}, {%0,%1,%2,%3};"
        : "+f"(d[0]), "+f"(d[1]), "+f"(d[2]), "+f"(d[3])
        : "r"(a[0]), "r"(a[1]), "r"(a[2]), "r"(a[3]), "r"(b[0]), "r"(b[1]));
}

__device__ __forceinline__ float ex2a(float x) {
    float y; asm("ex2.approx.f32 %0, %1;" : "=f"(y) : "f"(x)); return y;
}
__device__ __forceinline__ float rcpa(float x) {
    float y; asm("rcp.approx.f32 %0, %1;" : "=f"(y) : "f"(x)); return y;
}

__device__ __forceinline__ unsigned short h16_bits(__half h) {
    return *reinterpret_cast<unsigned short*>(&h);
}

// ---------------------------------------------------------------------------
// Kernel 0: weight prep. Wt[n][k] = fp16(W[k][u]) transposed.
// ---------------------------------------------------------------------------
__global__ __launch_bounds__(256) void bru_wprep(
    const float* __restrict__ kz, const float* __restrict__ kr, const float* __restrict__ kh)
{
    int i = blockIdx.x * 256 + threadIdx.x;       // [0, 768*256)
    int w = i >> 16;
    int k = (i >> 8) & 255;
    int u = i & 255;
    const float* W = (w == 0) ? kz : (w == 1) ? kr : kh;
    float v = W[k * 256 + u];
    int n = w * 256 + u;
    g_wt[n * 256 + k] = __float2half_rn(v);
}

// ---------------------------------------------------------------------------
// Kernel A: mma.sync fp16-split GEMM.  C[M,768] = X[M,256] @ Wt^T
//   A = Ah + Al (both fp16, exact to 2^-22); B = fp16 only.
//   2 passes: Ah*Bh + Al*Bh  (error = A*(B - fp16(B)) ~ 2.8e-4 rel RMS).
//   BM=128, BN=128, BK=32, 256 thr, 8 warps (4m x 2n), warp tile m32 x n64.
// ---------------------------------------------------------------------------
#define BM 128
#define BN 128
#define BK 32
#define RS 40                        // row stride in fp16 elems (80 B)
#define TILE_B (128 * RS * 2)        // 10240 B per array
#define STAGE_B (3 * TILE_B)         // Ahi, Alo, Bhi = 30720 B
#define SMEM_SZ (2 * STAGE_B)        // 61440 B

__global__ __launch_bounds__(256, 2) void bru_gemm_mma(const float* __restrict__ X)
{
    extern __shared__ char sm[];
    const uint32_t smb = smem_u32(sm);
    const int tid  = threadIdx.x;
    const int wid  = tid >> 5;
    const int lane = tid & 31;

    const int nt = blockIdx.x;            // 0..5 over N=768
    const int m0 = blockIdx.y * BM;
    const int n0 = nt * BN;

    const int wm = (wid >> 1) * 32;
    const int wn = (wid & 1) * 64;

    auto OA_HI = [&](int s) { return smb + s * STAGE_B; };
    auto OA_LO = [&](int s) { return smb + s * STAGE_B + TILE_B; };
    auto OB_HI = [&](int s) { return smb + s * STAGE_B + 2 * TILE_B; };

    float4 areg[4];
    auto ldgA = [&](int c) {
        const int kc = c * BK;
#pragma unroll
        for (int i = 0; i < 4; i++) {
            int s = i * 256 + tid;
            int row = s >> 3, c4 = s & 7;
            areg[i] = *(const float4*)(X + (size_t)(m0 + row) * D_DIM + kc + c4 * 4);
        }
    };
    auto stsA = [&](int st) {
#pragma unroll
        for (int i = 0; i < 4; i++) {
            int s = i * 256 + tid;
            int row = s >> 3, c4 = s & 7;
            uint32_t off = (uint32_t)(row * (RS * 2) + c4 * 8);
            float f[4] = {areg[i].x, areg[i].y, areg[i].z, areg[i].w};
            unsigned short h[4], l[4];
#pragma unroll
            for (int j = 0; j < 4; j++) {
                __half hh = __float2half_rn(f[j]);
                h[j] = h16_bits(hh);
                l[j] = h16_bits(__float2half_rn(f[j] - __half2float(hh)));
            }
            uint32_t ph0 = (uint32_t)h[0] | ((uint32_t)h[1] << 16);
            uint32_t ph1 = (uint32_t)h[2] | ((uint32_t)h[3] << 16);
            uint32_t pl0 = (uint32_t)l[0] | ((uint32_t)l[1] << 16);
            uint32_t pl1 = (uint32_t)l[2] | ((uint32_t)l[3] << 16);
            asm volatile("st.shared.v2.b32 [%0], {%1, %2};" :: "r"(OA_HI(st) + off), "r"(ph0), "r"(ph1) : "memory");
            asm volatile("st.shared.v2.b32 [%0], {%1, %2};" :: "r"(OA_LO(st) + off), "r"(pl0), "r"(pl1) : "memory");
        }
    };
    // B tile: 128 n-rows x 32 k fp16 = 512 x 16B granules / 256 thr = 2 each
    auto cpB = [&](int c, int st) {
        const int kc = c * BK;
#pragma unroll
        for (int i = 0; i < 2; i++) {
            int g = i * 256 + tid;
            int row = g >> 2, seg = g & 3;
            size_t e = (size_t)(n0 + row) * D_DIM + kc + seg * 8;
            uint32_t off = (uint32_t)(row * (RS * 2) + seg * 16);
            CP_ASYNC16(OB_HI(st) + off, (const char*)g_wt + e * 2);
        }
        CP_ASYNC_COMMIT();
    };

    ldgA(0);
    cpB(0, 0);
    stsA(0);
    CP_ASYNC_WAIT_ALL();
    __syncthreads();

    float acc[2][8][4];
#pragma unroll
    for (int mi = 0; mi < 2; mi++)
#pragma unroll
        for (int ni = 0; ni < 8; ni++)
#pragma unroll
            for (int r = 0; r < 4; r++) acc[mi][ni][r] = 0.0f;

    const int lrow = lane & 15;
    const int lhal = (lane >> 4) << 4;

    for (int c = 0; c < 8; c++) {
        const int st = c & 1;
        if (c < 7) { cpB(c + 1, st ^ 1); ldgA(c + 1); }

#pragma unroll
        for (int kk = 0; kk < 2; kk++) {
            const uint32_t kb = (uint32_t)(kk * 32);
            uint32_t ah[2][4], al[2][4], bh[4][4];
#pragma unroll
            for (int mi = 0; mi < 2; mi++) {
                uint32_t ra = (uint32_t)((wm + mi * 16 + lrow) * (RS * 2)) + kb + lhal;
                LDMATRIX_X4(ah[mi][0], ah[mi][1], ah[mi][2], ah[mi][3], OA_HI(st) + ra);
                LDMATRIX_X4(al[mi][0], al[mi][1], al[mi][2], al[mi][3], OA_LO(st) + ra);
            }
#pragma unroll
            for (int nj = 0; nj < 4; nj++) {
                uint32_t rb = (uint32_t)((wn + nj * 16 + lrow) * (RS * 2)) + kb + lhal;
                LDMATRIX_X4(bh[nj][0], bh[nj][1], bh[nj][2], bh[nj][3], OB_HI(st) + rb);
            }
#pragma unroll
            for (int mi = 0; mi < 2; mi++)
#pragma unroll
                for (int nj = 0; nj < 4; nj++) {
                    uint32_t b0h[2] = {bh[nj][0], bh[nj][2]};
                    uint32_t b1h[2] = {bh[nj][1], bh[nj][3]};
                    mma_f16(acc[mi][nj * 2 + 0], ah[mi], b0h);
                    mma_f16(acc[mi][nj * 2 + 0], al[mi], b0h);
                    mma_f16(acc[mi][nj * 2 + 1], ah[mi], b1h);
                    mma_f16(acc[mi][nj * 2 + 1], al[mi], b1h);
                }
        }

        if (c < 7) {
            stsA(st ^ 1);
            CP_ASYNC_WAIT_ALL();
            __syncthreads();
        }
    }

    const int w = nt >> 1;
    const int u0 = (nt & 1) * BN;
    float* Out = g_proj + (size_t)w * M_TOT * U_DIM;

    const int trow = lane >> 2;
    const int tcol = (lane & 3) * 2;
#pragma unroll
    for (int mi = 0; mi < 2; mi++)
#pragma unroll
        for (int ni = 0; ni < 8; ni++) {
            int r = m0 + wm + mi * 16 + trow;
            int cc = u0 + wn + ni * 8 + tcol;
            float2 v0 = make_float2(acc[mi][ni][0], acc[mi][ni][1]);
            float2 v1 = make_float2(acc[mi][ni][2], acc[mi][ni][3]);
            *(float2*)(Out + (size_t)r * U_DIM + cc) = v0;
            *(float2*)(Out + (size_t)(r + 8) * U_DIM + cc) = v1;
        }
}

// ---------------------------------------------------------------------------
// Kernel B: sequential scan.  PF=16 register prefetch; exp2-domain math.
// (known-good ~277 us; untouched)
// ---------------------------------------------------------------------------
#define PF 16

__global__ __launch_bounds__(256) void bru_scan(
    const float* __restrict__ mz, const float* __restrict__ mr,
    const float* __restrict__ bz, const float* __restrict__ br,
    const float* __restrict__ bh,
    float* __restrict__ out)
{
    const int b = blockIdx.x;        // batch
    const int u = threadIdx.x;       // unit

    const size_t base = (size_t)b * T_TOT * U_DIM + u;
    const float* __restrict__ pz = g_proj + base;
    const float* __restrict__ pr = g_proj + (size_t)1 * M_TOT * U_DIM + base;
    const float* __restrict__ ph = g_proj + (size_t)2 * M_TOT * U_DIM + base;
    float* __restrict__ po = out + base;

    const float C2 = 2.8853900817779268f;    // 2*log2(e)
    const float CN = -1.4426950408889634f;   // -log2(e)

    const float mr2 = mr[u] * C2, br2 = br[u] * C2;
    const float mzn = mz[u] * CN, bzn = bz[u] * CN;
    const float bh2 = bh[u] * C2;

    float qz[PF], qr[PF], qh[PF];
#pragma unroll
    for (int j = 0; j < PF; j++) {
        qz[j] = pz[(size_t)j * U_DIM];
        qr[j] = pr[(size_t)j * U_DIM];
        qh[j] = ph[(size_t)j * U_DIM];
    }

    float h = 0.0f;

#pragma unroll 1
    for (int t0 = 0; t0 < T_TOT - PF; t0 += PF) {
#pragma unroll
        for (int j = 0; j < PF; j++) {
            const float vz = qz[j], vr = qr[j], vh = qh[j];
            qz[j] = pz[(size_t)(j + PF) * U_DIM];
            qr[j] = pr[(size_t)(j + PF) * U_DIM];
            qh[j] = ph[(size_t)(j + PF) * U_DIM];

            const float hs   = h * C2;
            const float hbase= fmaf(vh, C2, bh2);
            const float pre2 = fmaf(2.0f, hs, hbase);
            const float hm1  = h - 1.0f;

            const float ar2 = fmaf(h, mr2, fmaf(vr, C2, br2));
            const float tr  = rcpa(ex2a(ar2) + 1.0f);

            const float azn = fmaf(h, mzn, fmaf(vz, CN, bzn));
            const float z   = rcpa(ex2a(azn) + 1.0f);

            const float ah2 = fmaf(-2.0f * tr, hs, pre2);
            const float th  = rcpa(ex2a(ah2) + 1.0f);
            const float hh  = fmaf(-2.0f, th, 1.0f);
            const float d   = fmaf(2.0f, th, hm1);

            h = fmaf(z, d, hh);
            po[(size_t)j * U_DIM] = h;
        }
        pz += PF * U_DIM; pr += PF * U_DIM; ph += PF * U_DIM; po += PF * U_DIM;
    }

    // tail: last PF steps, no prefetch
#pragma unroll
    for (int j = 0; j < PF; j++) {
        const float hs   = h * C2;
        const float hbase= fmaf(qh[j], C2, bh2);
        const float pre2 = fmaf(2.0f, hs, hbase);
        const float hm1  = h - 1.0f;

        const float ar2 = fmaf(h, mr2, fmaf(qr[j], C2, br2));
        const float tr  = rcpa(ex2a(ar2) + 1.0f);

        const float azn = fmaf(h, mzn, fmaf(qz[j], CN, bzn));
        const float z   = rcpa(ex2a(azn) + 1.0f);

        const float ah2 = fmaf(-2.0f * tr, hs, pre2);
        const float th  = rcpa(ex2a(ah2) + 1.0f);
        const float hh  = fmaf(-2.0f, th, 1.0f);
        const float d   = fmaf(2.0f, th, hm1);

        h = fmaf(z, d, hh);
        po[(size_t)j * U_DIM] = h;
    }
}

// ---------------------------------------------------------------------------
extern "C" void kernel_launch(void* const* d_in, const int* in_sizes, int n_in,
                              void* d_out, int out_size)
{
    const float* x  = (const float*)d_in[0];
    const float* kz = (const float*)d_in[1];
    const float* kr = (const float*)d_in[2];
    const float* kh = (const float*)d_in[3];
    const float* mz = (const float*)d_in[4];
    const float* mr = (const float*)d_in[5];
    const float* bz = (const float*)d_in[6];
    const float* br = (const float*)d_in[7];
    const float* bh = (const float*)d_in[8];
    float* out = (float*)d_out;

    static bool init_done = (cudaFuncSetAttribute(bru_gemm_mma,
        cudaFuncAttributeMaxDynamicSharedMemorySize, SMEM_SZ) == cudaSuccess);
    (void)init_done;

    bru_wprep<<<768, 256>>>(kz, kr, kh);
    dim3 gg(6, M_TOT / BM);
    bru_gemm_mma<<<gg, 256, SMEM_SZ>>>(x);
    bru_scan<<<B_TOT, 256>>>(mz, mr, bz, br, bh, out);
}